// round 1
// baseline (speedup 1.0000x reference)
#include <cuda_runtime.h>
#include <cuda_bf16.h>
#include <cstdint>

// MeanStiffRegularizer: segment-mean over 2^25 elements into 256 segments,
// then loss = mean((mean_w - target)^2) * 0.01.
//
// Strategy: per-CTA shared histogram of packed 64-bit (sum<<24 | count)
// accumulators, one smem atomicAdd(u64) per element. Fixed-point sum via the
// float "magic constant" trick (FFMA + IADD, no F2I). Deterministic integer
// global accumulation, then a tiny finalize kernel.

#define NUM_UNIQUE 256
#define THREADS 256
#define MAX_BLOCKS 1184   // 148 SMs * 8

// Global scratch (allocation-free per harness rules)
__device__ unsigned long long g_sumfix[NUM_UNIQUE];
__device__ unsigned int       g_cnt[NUM_UNIQUE];

// Fixed-point: round(x * 2^18) + 2^22, computed as float-bit trick.
// f = x*2^18 + 1.5*2^23  -> bits = 0x4B400000 + round(x*2^18)  (valid |x| < 16)
// u = bits - 0x4B000000  = round(x*2^18) + 2^22  in [0, 2^23)
__global__ void msr_zero_kernel() {
    int t = blockIdx.x * blockDim.x + threadIdx.x;
    if (t < NUM_UNIQUE) {
        g_sumfix[t] = 0ull;
        g_cnt[t] = 0u;
    }
}

__global__ __launch_bounds__(THREADS)
void msr_hist_kernel(const float* __restrict__ x,
                     const int* __restrict__ idx,
                     int n) {
    __shared__ unsigned long long hist[NUM_UNIQUE];

    // zero block-local histogram
    for (int b = threadIdx.x; b < NUM_UNIQUE; b += THREADS)
        hist[b] = 0ull;
    __syncthreads();

    const int nvec = n >> 2;
    const float4* x4 = reinterpret_cast<const float4*>(x);
    const int4*   i4 = reinterpret_cast<const int4*>(idx);

    const int stride = gridDim.x * blockDim.x;
    for (int i = blockIdx.x * blockDim.x + threadIdx.x; i < nvec; i += stride) {
        float4 xv = x4[i];
        int4   iv = i4[i];

        #pragma unroll
        for (int j = 0; j < 4; j++) {
            float v;
            int   b;
            switch (j) {
                case 0: v = xv.x; b = iv.x; break;
                case 1: v = xv.y; b = iv.y; break;
                case 2: v = xv.z; b = iv.z; break;
                default: v = xv.w; b = iv.w; break;
            }
            float f = fmaf(v, 262144.0f, 12582912.0f);     // x*2^18 + 1.5*2^23
            unsigned u = __float_as_uint(f) - 0x4B000000u;  // round(x*2^18)+2^22
            unsigned long long p = ((unsigned long long)u << 24) | 1ull;
            atomicAdd(&hist[b & (NUM_UNIQUE - 1)], p);
        }
    }

    // scalar tail (n not multiple of 4): block 0 only
    if (blockIdx.x == 0) {
        for (int i = (nvec << 2) + threadIdx.x; i < n; i += THREADS) {
            float v = x[i];
            int   b = idx[i];
            float f = fmaf(v, 262144.0f, 12582912.0f);
            unsigned u = __float_as_uint(f) - 0x4B000000u;
            unsigned long long p = ((unsigned long long)u << 24) | 1ull;
            atomicAdd(&hist[b & (NUM_UNIQUE - 1)], p);
        }
    }

    __syncthreads();

    // flush: de-bias sum field, integer global atomics (deterministic)
    for (int b = threadIdx.x; b < NUM_UNIQUE; b += THREADS) {
        unsigned long long p = hist[b];
        unsigned cnt = (unsigned)(p & 0xFFFFFFull);
        if (cnt) {
            long long sumfix = (long long)(p >> 24) - ((long long)cnt << 22);
            atomicAdd(&g_sumfix[b], (unsigned long long)sumfix);
            atomicAdd(&g_cnt[b], cnt);
        }
    }
}

__global__ __launch_bounds__(NUM_UNIQUE)
void msr_finalize_kernel(const float* __restrict__ target_mean,
                         float* __restrict__ out) {
    __shared__ float red[NUM_UNIQUE];
    int t = threadIdx.x;

    long long s = (long long)g_sumfix[t];
    unsigned  c = g_cnt[t];

    // mean = (s * 2^-18) / max(c, 1); empty segments yield 0 (s==0 there)
    double cnt = (c > 0u) ? (double)c : 1.0;
    float mean = (float)(((double)s * (1.0 / 262144.0)) / cnt);

    float dev = mean - target_mean[t];
    red[t] = dev * dev;
    __syncthreads();

    // tree reduce over 256
    #pragma unroll
    for (int off = NUM_UNIQUE / 2; off >= 32; off >>= 1) {
        if (t < off) red[t] += red[t + off];
        __syncthreads();
    }
    if (t < 32) {
        float v = red[t];
        #pragma unroll
        for (int off = 16; off > 0; off >>= 1)
            v += __shfl_down_sync(0xFFFFFFFFu, v, off);
        if (t == 0)
            out[0] = v * (0.01f / (float)NUM_UNIQUE);
    }
}

extern "C" void kernel_launch(void* const* d_in, const int* in_sizes, int n_in,
                              void* d_out, int out_size) {
    const float* x           = (const float*)d_in[0];
    const int*   idx         = (const int*)d_in[1];
    const float* target_mean = (const float*)d_in[2];
    float*       out         = (float*)d_out;
    int n = in_sizes[0];

    msr_zero_kernel<<<1, NUM_UNIQUE>>>();

    int nvec = n >> 2;
    int blocks = (nvec + THREADS - 1) / THREADS;
    if (blocks > MAX_BLOCKS) blocks = MAX_BLOCKS;
    if (blocks < 1) blocks = 1;
    msr_hist_kernel<<<blocks, THREADS>>>(x, idx, n);

    msr_finalize_kernel<<<1, NUM_UNIQUE>>>(target_mean, out);
}

// round 2
// speedup vs baseline: 1.0998x; 1.0998x over previous
#include <cuda_runtime.h>
#include <cuda_bf16.h>
#include <cstdint>

// MeanStiffRegularizer: segment-mean over 2^25 elements into 256 segments,
// then loss = mean((mean_w - target)^2) * 0.01.
//
// Round 2: the smem atomic unit was the bottleneck (~1.65 cyc/elem = spread
// ATOMS floor). Split the element stream 50/50 between:
//   - smem ATOMS.64 into a per-CTA packed histogram (as before)
//   - global REDG.ADD.64 into a 64-way replicated global table (L2 atomic
//     ALUs, no return trip -> SM pays issue cost only)
// The two accumulate paths use independent hardware and should overlap.
// Packed u64 format everywhere: (biased_sum << 24) | count, fully integer
// deterministic.

#define NUM_UNIQUE 256
#define THREADS 256
#define MAX_BLOCKS 1184   // 148 SMs * 8
#define R_REPL 64         // replication of the global REDG table

// Global scratch (allocation-free per harness rules)
__device__ unsigned long long g_part[R_REPL * NUM_UNIQUE]; // REDG targets (packed)
__device__ unsigned long long g_sumfix[NUM_UNIQUE];        // de-biased sums (smem path)
__device__ unsigned int       g_cnt[NUM_UNIQUE];           // counts (smem path)

// Fixed-point: round(x * 2^18) + 2^22 via float magic constant.
// f = x*2^18 + 1.5*2^23 -> bits = 0x4B400000 + round(x*2^18)  (valid |x| < 16)
// u = bits - 0x4B000000 = round(x*2^18) + 2^22 in [0, 2^23)
__device__ __forceinline__ unsigned long long pack_elem(float v) {
    float f = fmaf(v, 262144.0f, 12582912.0f);
    unsigned u = __float_as_uint(f) - 0x4B000000u;
    return ((unsigned long long)u << 24) | 1ull;
}

__global__ void msr_zero_kernel() {
    int t = blockIdx.x * blockDim.x + threadIdx.x;
    int stride = gridDim.x * blockDim.x;
    for (int i = t; i < R_REPL * NUM_UNIQUE; i += stride)
        g_part[i] = 0ull;
    if (t < NUM_UNIQUE) {
        g_sumfix[t] = 0ull;
        g_cnt[t] = 0u;
    }
}

__global__ __launch_bounds__(THREADS)
void msr_hist_kernel(const float* __restrict__ x,
                     const int* __restrict__ idx,
                     int n) {
    __shared__ unsigned long long hist[NUM_UNIQUE];

    for (int b = threadIdx.x; b < NUM_UNIQUE; b += THREADS)
        hist[b] = 0ull;
    __syncthreads();

    unsigned long long* part = &g_part[(blockIdx.x & (R_REPL - 1)) * NUM_UNIQUE];

    const int nvec = n >> 2;
    const float4* x4 = reinterpret_cast<const float4*>(x);
    const int4*   i4 = reinterpret_cast<const int4*>(idx);

    const int stride = gridDim.x * blockDim.x;
    for (int i = blockIdx.x * blockDim.x + threadIdx.x; i < nvec; i += stride) {
        float4 xv = x4[i];
        int4   iv = i4[i];

        // elements 0,2 -> smem ATOMS path; elements 1,3 -> global REDG path
        atomicAdd(&hist[iv.x & (NUM_UNIQUE - 1)], pack_elem(xv.x));
        atomicAdd(&part[iv.y & (NUM_UNIQUE - 1)], pack_elem(xv.y));
        atomicAdd(&hist[iv.z & (NUM_UNIQUE - 1)], pack_elem(xv.z));
        atomicAdd(&part[iv.w & (NUM_UNIQUE - 1)], pack_elem(xv.w));
    }

    // scalar tail (n not multiple of 4): block 0 only, smem path
    if (blockIdx.x == 0) {
        for (int i = (nvec << 2) + threadIdx.x; i < n; i += THREADS) {
            atomicAdd(&hist[idx[i] & (NUM_UNIQUE - 1)], pack_elem(x[i]));
        }
    }

    __syncthreads();

    // flush smem histogram: de-bias, integer global reductions
    for (int b = threadIdx.x; b < NUM_UNIQUE; b += THREADS) {
        unsigned long long p = hist[b];
        unsigned cnt = (unsigned)(p & 0xFFFFFFull);
        if (cnt) {
            long long sumfix = (long long)(p >> 24) - ((long long)cnt << 22);
            atomicAdd(&g_sumfix[b], (unsigned long long)sumfix);
            atomicAdd(&g_cnt[b], cnt);
        }
    }
}

__global__ __launch_bounds__(NUM_UNIQUE)
void msr_finalize_kernel(const float* __restrict__ target_mean,
                         float* __restrict__ out) {
    __shared__ float red[NUM_UNIQUE];
    int t = threadIdx.x;

    long long          s = (long long)g_sumfix[t];
    unsigned long long c = (unsigned long long)g_cnt[t];

    // fold in the 64 REDG replicas (packed format)
    #pragma unroll 8
    for (int r = 0; r < R_REPL; r++) {
        unsigned long long p = g_part[r * NUM_UNIQUE + t];
        unsigned long long cnt = p & 0xFFFFFFull;
        s += (long long)(p >> 24) - (long long)(cnt << 22);
        c += cnt;
    }

    // mean = (s * 2^-18) / max(c, 1); empty segments yield 0 (s==0 there)
    double cnt = (c > 0ull) ? (double)c : 1.0;
    float mean = (float)(((double)s * (1.0 / 262144.0)) / cnt);

    float dev = mean - target_mean[t];
    red[t] = dev * dev;
    __syncthreads();

    #pragma unroll
    for (int off = NUM_UNIQUE / 2; off >= 32; off >>= 1) {
        if (t < off) red[t] += red[t + off];
        __syncthreads();
    }
    if (t < 32) {
        float v = red[t];
        #pragma unroll
        for (int off = 16; off > 0; off >>= 1)
            v += __shfl_down_sync(0xFFFFFFFFu, v, off);
        if (t == 0)
            out[0] = v * (0.01f / (float)NUM_UNIQUE);
    }
}

extern "C" void kernel_launch(void* const* d_in, const int* in_sizes, int n_in,
                              void* d_out, int out_size) {
    const float* x           = (const float*)d_in[0];
    const int*   idx         = (const int*)d_in[1];
    const float* target_mean = (const float*)d_in[2];
    float*       out         = (float*)d_out;
    int n = in_sizes[0];

    msr_zero_kernel<<<64, 256>>>();

    int nvec = n >> 2;
    int blocks = (nvec + THREADS - 1) / THREADS;
    if (blocks > MAX_BLOCKS) blocks = MAX_BLOCKS;
    if (blocks < 1) blocks = 1;
    msr_hist_kernel<<<blocks, THREADS>>>(x, idx, n);

    msr_finalize_kernel<<<1, NUM_UNIQUE>>>(target_mean, out);
}